// round 15
// baseline (speedup 1.0000x reference)
#include <cuda_runtime.h>
#include <cuda_fp16.h>
#include <mma.h>

using namespace nvcuda;

// GCN: h1 = relu(A_hat @ (x@W1) + b1); h2 = A_hat @ (h1@W2) + b2
// out[g] = mean_i dot(h2[i], Wl) + bl
// Layer 2 linear => w2l = W2@Wl collapses it to a scalar CSR aggregation.
// Layer-1 gather epilogue emits w[d] = dinv[d]*dot(relu(acc+b1), w2l).
// x@W1 via fp16 HMMA (stream 2, forked immediately — no adjacency dep).
// Batch counting + gsum/cnt zeroing live on stream 2 (consumed post-join),
// so k_hist is a pure RED pass (R13-measured 13.5us vs 29.8us).

#define NMAX 100000
#define EMAX 1600000
#define GMAX 512
#define FEAT 128

__device__ __half g_bufH[(size_t)NMAX * FEAT];  // x @ W1 (fp16 storage)
__device__ float g_w[NMAX];                      // dinv[i] * dot(h1[i], w2l)
__device__ float g_dinv[NMAX];
__device__ float g_w2l[FEAT];
__device__ float g_b2wl;                         // dot(b2, Wl)
__device__ float g_gsum[GMAX];
__device__ float g_cnt[GMAX];                    // nodes per graph

__device__ int g_degi[NMAX];      // incoming-edge count (no self loop)
__device__ int g_rowstart[NMAX];  // CSR row offsets
__device__ int g_cursor[NMAX];    // absolute fill cursors
__device__ int g_csrc[EMAX];      // CSR: source node per incoming edge
__device__ int g_ctr;             // slot allocator counter

// ---------------------------------------------------------------------------
__global__ void k_init(int n) {
    int i = blockIdx.x * blockDim.x + threadIdx.x;
    if (i < n) g_degi[i] = 0;
    if (i == 0) g_ctr = 0;
}

// Degree histogram (RED only, int4 grid-stride). No batch counting here.
__global__ void k_hist(const int* __restrict__ dst, int E) {
    int stride = gridDim.x * blockDim.x;
    int t = blockIdx.x * blockDim.x + threadIdx.x;
    int E4 = E >> 2;
    const int4* d4 = (const int4*)dst;
    for (int e = t; e < E4; e += stride) {
        int4 v = d4[e];
        atomicAdd(&g_degi[v.x], 1); atomicAdd(&g_degi[v.y], 1);
        atomicAdd(&g_degi[v.z], 1); atomicAdd(&g_degi[v.w], 1);
    }
    for (int e = E4 * 4 + t; e < E; e += stride)
        atomicAdd(&g_degi[dst[e]], 1);
}

// Stream-2: w2l = W2@Wl, b2wl = dot(b2,Wl), zero gsum + cnt.
__global__ __launch_bounds__(128) void k_w2l(const float* __restrict__ W2,
                                             const float* __restrict__ Wl,
                                             const float* __restrict__ b2) {
    __shared__ float wls[FEAT];
    int t = threadIdx.x;
    wls[t] = Wl[t];
#pragma unroll
    for (int q = 0; q < 4; q++) { g_gsum[t + q * 128] = 0.0f; g_cnt[t + q * 128] = 0.0f; }
    __syncthreads();
    float acc = 0.0f;
    const float* row = W2 + (size_t)t * FEAT;
#pragma unroll 8
    for (int j = 0; j < FEAT; j++) acc += row[j] * wls[j];
    g_w2l[t] = acc;
    if (t == 0) {
        float c = 0.0f;
        for (int j = 0; j < FEAT; j++) c += b2[j] * wls[j];
        g_b2wl = c;
    }
}

// Stream-2: nodes-per-graph histogram (consumed only by k_out, after join).
__global__ void k_cntbatch(const int* __restrict__ batch, int n) {
    int stride = gridDim.x * blockDim.x;
    for (int i = blockIdx.x * blockDim.x + threadIdx.x; i < n; i += stride)
        atomicAdd(&g_cnt[batch[i]], 1.0f);
}

// CSR slot allocation, warp-aggregated (one g_ctr atomic per warp) + dinv.
__global__ void k_alloc(int n) {
    int i = blockIdx.x * blockDim.x + threadIdx.x;
    int lane = threadIdx.x & 31;
    int deg = (i < n) ? g_degi[i] : 0;
    int incl = deg;
#pragma unroll
    for (int off = 1; off < 32; off <<= 1) {
        int v = __shfl_up_sync(0xFFFFFFFFu, incl, off);
        if (lane >= off) incl += v;
    }
    int total = __shfl_sync(0xFFFFFFFFu, incl, 31);
    int base = 0;
    if (lane == 31 && total > 0) base = atomicAdd(&g_ctr, total);
    base = __shfl_sync(0xFFFFFFFFu, base, 31);
    if (i < n) {
        int rs = base + incl - deg;
        g_rowstart[i] = rs;
        g_cursor[i] = rs;
        g_dinv[i] = rsqrtf(1.0f + (float)deg);
    }
}

// CSR fill (cursor atomics, int4 grid-stride with 4x batching).
__global__ void k_fill(const int* __restrict__ src, const int* __restrict__ dst, int E) {
    int stride = gridDim.x * blockDim.x;
    int t = blockIdx.x * blockDim.x + threadIdx.x;
    int E4 = E >> 2;
    const int4* d4 = (const int4*)dst;
    const int4* s4 = (const int4*)src;
    int e = t;
    for (; e + 3 * stride < E4; e += 4 * stride) {
        int4 da = d4[e];
        int4 db = d4[e + stride];
        int4 dc = d4[e + 2 * stride];
        int4 dd = d4[e + 3 * stride];
        int4 sa = s4[e];
        int4 sb = s4[e + stride];
        int4 sc = s4[e + 2 * stride];
        int4 sd = s4[e + 3 * stride];
        g_csrc[atomicAdd(&g_cursor[da.x], 1)] = sa.x;
        g_csrc[atomicAdd(&g_cursor[da.y], 1)] = sa.y;
        g_csrc[atomicAdd(&g_cursor[da.z], 1)] = sa.z;
        g_csrc[atomicAdd(&g_cursor[da.w], 1)] = sa.w;
        g_csrc[atomicAdd(&g_cursor[db.x], 1)] = sb.x;
        g_csrc[atomicAdd(&g_cursor[db.y], 1)] = sb.y;
        g_csrc[atomicAdd(&g_cursor[db.z], 1)] = sb.z;
        g_csrc[atomicAdd(&g_cursor[db.w], 1)] = sb.w;
        g_csrc[atomicAdd(&g_cursor[dc.x], 1)] = sc.x;
        g_csrc[atomicAdd(&g_cursor[dc.y], 1)] = sc.y;
        g_csrc[atomicAdd(&g_cursor[dc.z], 1)] = sc.z;
        g_csrc[atomicAdd(&g_cursor[dc.w], 1)] = sc.w;
        g_csrc[atomicAdd(&g_cursor[dd.x], 1)] = sd.x;
        g_csrc[atomicAdd(&g_cursor[dd.y], 1)] = sd.y;
        g_csrc[atomicAdd(&g_cursor[dd.z], 1)] = sd.z;
        g_csrc[atomicAdd(&g_cursor[dd.w], 1)] = sd.w;
    }
    for (; e < E4; e += stride) {
        int4 dv = d4[e];
        int4 sv = s4[e];
        g_csrc[atomicAdd(&g_cursor[dv.x], 1)] = sv.x;
        g_csrc[atomicAdd(&g_cursor[dv.y], 1)] = sv.y;
        g_csrc[atomicAdd(&g_cursor[dv.z], 1)] = sv.z;
        g_csrc[atomicAdd(&g_cursor[dv.w], 1)] = sv.w;
    }
    for (int q = E4 * 4 + t; q < E; q += stride)
        g_csrc[atomicAdd(&g_cursor[dst[q]], 1)] = src[q];
}

// ---------------------------------------------------------------------------
// HMMA GEMM: C[M,128] = fp16(A[M,128]) @ fp16(B[128,128]), fp32 accum,
// fp16 output. BM=64 rows/block, full K=128 resident in smem (48KB).
__global__ __launch_bounds__(256) void k_hgemm(const float* __restrict__ A,
                                               const float* __restrict__ B,
                                               __half* __restrict__ C, int M) {
    __shared__ __half Ah[64 * 128];
    __shared__ __half Bh[128 * 128];
    const int tid = threadIdx.x;
    const int block_row = blockIdx.x * 64;

    for (int i = tid; i < 4096; i += 256) {
        float4 v = ((const float4*)B)[i];
        ((__half2*)Bh)[i * 2 + 0] = __floats2half2_rn(v.x, v.y);
        ((__half2*)Bh)[i * 2 + 1] = __floats2half2_rn(v.z, v.w);
    }
    for (int i = tid; i < 2048; i += 256) {
        int row = i >> 5;
        float4 v = make_float4(0.f, 0.f, 0.f, 0.f);
        int gr = block_row + row;
        if (gr < M) v = ((const float4*)(A + (size_t)gr * 128))[i & 31];
        ((__half2*)Ah)[i * 2 + 0] = __floats2half2_rn(v.x, v.y);
        ((__half2*)Ah)[i * 2 + 1] = __floats2half2_rn(v.z, v.w);
    }
    __syncthreads();

    const int warp = tid >> 5;
    const int wm = warp >> 2;
    const int wn = warp & 3;

    wmma::fragment<wmma::accumulator, 16, 16, 16, float> acc[2][2];
#pragma unroll
    for (int i = 0; i < 2; i++)
#pragma unroll
        for (int j = 0; j < 2; j++) wmma::fill_fragment(acc[i][j], 0.0f);

#pragma unroll
    for (int k = 0; k < 128; k += 16) {
        wmma::fragment<wmma::matrix_a, 16, 16, 16, __half, wmma::row_major> a[2];
        wmma::fragment<wmma::matrix_b, 16, 16, 16, __half, wmma::row_major> b[2];
#pragma unroll
        for (int i = 0; i < 2; i++)
            wmma::load_matrix_sync(a[i], Ah + (wm * 32 + i * 16) * 128 + k, 128);
#pragma unroll
        for (int j = 0; j < 2; j++)
            wmma::load_matrix_sync(b[j], Bh + k * 128 + wn * 32 + j * 16, 128);
#pragma unroll
        for (int i = 0; i < 2; i++)
#pragma unroll
            for (int j = 0; j < 2; j++)
                wmma::mma_sync(acc[i][j], a[i], b[j], acc[i][j]);
    }
    __syncthreads();

    float* Cs = (float*)Bh;
#pragma unroll
    for (int i = 0; i < 2; i++)
#pragma unroll
        for (int j = 0; j < 2; j++)
            wmma::store_matrix_sync(Cs + (wm * 32 + i * 16) * 128 + wn * 32 + j * 16,
                                    acc[i][j], 128, wmma::mem_row_major);
    __syncthreads();

    for (int i = tid; i < 2048; i += 256) {
        int row = i >> 5;
        int gr = block_row + row;
        if (gr < M) {
            float4 v = ((const float4*)Cs)[i];
            __half2 h0 = __floats2half2_rn(v.x, v.y);
            __half2 h1 = __floats2half2_rn(v.z, v.w);
            uint2 o;
            o.x = *(unsigned*)&h0;
            o.y = *(unsigned*)&h1;
            ((uint2*)(C + (size_t)gr * 128))[i & 31] = o;
        }
    }
}

// ---------------------------------------------------------------------------
// CSR gather: 2 nodes per warp, 16 lanes x uint4 (8 halves) per node row.
//   acc = h[d]*dinv[d]^2 + sum_{s in N(d)} h[s]*dinv[s]*dinv[d]
//   g_w[d] = dinv[d] * dot(relu(acc + b1), w2l)
__global__ void k_gather1(const __half* __restrict__ h,
                          const float* __restrict__ bias, int n) {
    const int lane = threadIdx.x & 31;
    const int half = lane >> 4;
    const int hl = lane & 15;
    int warp = (blockIdx.x * blockDim.x + threadIdx.x) >> 5;
    int nwarps = (gridDim.x * blockDim.x) >> 5;

    float4 b0 = ((const float4*)bias)[hl * 2 + 0];
    float4 b1v = ((const float4*)bias)[hl * 2 + 1];
    float4 w0 = ((const float4*)g_w2l)[hl * 2 + 0];
    float4 w1 = ((const float4*)g_w2l)[hl * 2 + 1];

    for (int d = warp * 2 + half; d < n; d += nwarps * 2) {
        float dd = g_dinv[d];
        uint4 raw = ((const uint4*)(h + (size_t)d * FEAT))[hl];
        float2 p0 = __half22float2(*(const __half2*)&raw.x);
        float2 p1 = __half22float2(*(const __half2*)&raw.y);
        float2 p2 = __half22float2(*(const __half2*)&raw.z);
        float2 p3 = __half22float2(*(const __half2*)&raw.w);
        float sl = dd * dd;
        float a0 = p0.x * sl, a1 = p0.y * sl, a2 = p1.x * sl, a3 = p1.y * sl;
        float a4 = p2.x * sl, a5 = p2.y * sl, a6 = p3.x * sl, a7 = p3.y * sl;

        int r0 = g_rowstart[d];
        int r1 = r0 + g_degi[d];
        for (int r = r0; r < r1; r++) {
            int s = g_csrc[r];
            float nrm = g_dinv[s] * dd;
            uint4 rv = ((const uint4*)(h + (size_t)s * FEAT))[hl];
            float2 q0 = __half22float2(*(const __half2*)&rv.x);
            float2 q1 = __half22float2(*(const __half2*)&rv.y);
            float2 q2 = __half22float2(*(const __half2*)&rv.z);
            float2 q3 = __half22float2(*(const __half2*)&rv.w);
            a0 += q0.x * nrm; a1 += q0.y * nrm;
            a2 += q1.x * nrm; a3 += q1.y * nrm;
            a4 += q2.x * nrm; a5 += q2.y * nrm;
            a6 += q3.x * nrm; a7 += q3.y * nrm;
        }
        float sdot;
        sdot  = fmaxf(a0 + b0.x, 0.f) * w0.x;
        sdot += fmaxf(a1 + b0.y, 0.f) * w0.y;
        sdot += fmaxf(a2 + b0.z, 0.f) * w0.z;
        sdot += fmaxf(a3 + b0.w, 0.f) * w0.w;
        sdot += fmaxf(a4 + b1v.x, 0.f) * w1.x;
        sdot += fmaxf(a5 + b1v.y, 0.f) * w1.y;
        sdot += fmaxf(a6 + b1v.z, 0.f) * w1.z;
        sdot += fmaxf(a7 + b1v.w, 0.f) * w1.w;
#pragma unroll
        for (int off = 8; off > 0; off >>= 1)
            sdot += __shfl_xor_sync(0xFFFFFFFFu, sdot, off);
        if (hl == 0) g_w[d] = dd * sdot;
    }
}

// Scalar aggregation + pool: gsum[batch[d]] += dinv[d]*(w[d] + sum_s w[s]).
__global__ void k_scalar(const int* __restrict__ batch, int n) {
    int stride = gridDim.x * blockDim.x;
    for (int d = blockIdx.x * blockDim.x + threadIdx.x; d < n; d += stride) {
        float s = g_w[d];
        int r0 = g_rowstart[d];
        int r1 = r0 + g_degi[d];
        for (int r = r0; r < r1; r++) s += g_w[g_csrc[r]];
        atomicAdd(&g_gsum[batch[d]], g_dinv[d] * s);
    }
}

// out[g] = gsum[g]/max(cnt,1) + dot(b2, Wl) + bl
__global__ void k_out(const float* __restrict__ bl, float* __restrict__ out) {
    int g = blockIdx.x * blockDim.x + threadIdx.x;
    if (g < GMAX)
        out[g] = g_gsum[g] / fmaxf(g_cnt[g], 1.0f) + g_b2wl + bl[0];
}

// ---------------------------------------------------------------------------
static cudaStream_t g_s2 = nullptr;
static cudaEvent_t g_evFork = nullptr, g_evJoin = nullptr;

extern "C" void kernel_launch(void* const* d_in, const int* in_sizes, int n_in,
                              void* d_out, int out_size) {
    const float* x     = (const float*)d_in[0];
    const int*   ei    = (const int*)d_in[1];
    const int*   batch = (const int*)d_in[3];
    const float* W1    = (const float*)d_in[4];
    const float* b1    = (const float*)d_in[5];
    const float* W2    = (const float*)d_in[6];
    const float* b2    = (const float*)d_in[7];
    const float* Wl    = (const float*)d_in[8];
    const float* bl    = (const float*)d_in[9];
    float* out = (float*)d_out;

    int n = in_sizes[0] / FEAT;
    int E = in_sizes[1] / 2;
    if (n > NMAX) n = NMAX;
    if (E > EMAX) E = EMAX;
    const int* src = ei;
    const int* dst = ei + E;

    __half* bufH;
    cudaGetSymbolAddress((void**)&bufH, g_bufH);

    if (!g_s2) {
        cudaStreamCreateWithFlags(&g_s2, cudaStreamNonBlocking);
        cudaEventCreateWithFlags(&g_evFork, cudaEventDisableTiming);
        cudaEventCreateWithFlags(&g_evJoin, cudaEventDisableTiming);
    }

    const int T = 256;
    int nBlocksN   = (n + T - 1) / T;
    int gemmBlocks = (n + 63) / 64;
    int E4 = E >> 2;
    int fillBlocks = (E4 + 2 * T - 1) / (2 * T);      // ~2 batched iters/thread

    // Fork: stream 2 — GEMM immediately (no adjacency dependency),
    // plus w2l and the batch histogram (all consumed only after the join).
    cudaEventRecord(g_evFork, 0);
    cudaStreamWaitEvent(g_s2, g_evFork, 0);
    k_w2l<<<1, 128, 0, g_s2>>>(W2, Wl, b2);
    k_hgemm<<<gemmBlocks, T, 0, g_s2>>>(x, W1, bufH, n);
    k_cntbatch<<<512, T, 0, g_s2>>>(batch, n);
    cudaEventRecord(g_evJoin, g_s2);

    // Main stream: compact CSR build (hist is now RED-only).
    k_init<<<nBlocksN, T>>>(n);
    k_hist<<<1024, T>>>(dst, E);
    k_alloc<<<nBlocksN, T>>>(n);
    k_fill<<<fillBlocks, T>>>(src, dst, E);

    // Join, then gather + scalar + head.
    cudaStreamWaitEvent(0, g_evJoin, 0);
    k_gather1<<<2048, T>>>(bufH, b1, n);
    k_scalar<<<1024, T>>>(batch, n);
    k_out<<<(GMAX + T - 1) / T, T>>>(bl, out);
}

// round 16
// speedup vs baseline: 1.5123x; 1.5123x over previous
#include <cuda_runtime.h>
#include <cuda_fp16.h>
#include <mma.h>

using namespace nvcuda;

// GCN: h1 = relu(A_hat @ (x@W1) + b1); h2 = A_hat @ (h1@W2) + b2
// out[g] = mean_i dot(h2[i], Wl) + bl
// Layer 2 linear => w2l = W2@Wl collapses it to a scalar CSR aggregation.
// Layer-1 gather epilogue emits w[d] = dinv[d]*dot(relu(acc+b1), w2l).
// x@W1 via fp16 HMMA (stream 2: w2l + hgemm ONLY — no concurrent atomics).
// k_hist is pure RED (measured 13.5us). Per-graph node counts come from
// binary search on the SORTED batch array inside k_out (no histogram).

#define NMAX 100000
#define EMAX 1600000
#define GMAX 512
#define FEAT 128

__device__ __half g_bufH[(size_t)NMAX * FEAT];  // x @ W1 (fp16 storage)
__device__ float g_w[NMAX];                      // dinv[i] * dot(h1[i], w2l)
__device__ float g_dinv[NMAX];
__device__ float g_w2l[FEAT];
__device__ float g_b2wl;                         // dot(b2, Wl)
__device__ float g_gsum[GMAX];

__device__ int g_degi[NMAX];      // incoming-edge count (no self loop)
__device__ int g_rowstart[NMAX];  // CSR row offsets
__device__ int g_cursor[NMAX];    // absolute fill cursors
__device__ int g_csrc[EMAX];      // CSR: source node per incoming edge
__device__ int g_ctr;             // slot allocator counter

// ---------------------------------------------------------------------------
__global__ void k_init(int n) {
    int i = blockIdx.x * blockDim.x + threadIdx.x;
    if (i < n) g_degi[i] = 0;
    if (i < GMAX) g_gsum[i] = 0.0f;
    if (i == 0) g_ctr = 0;
}

// Degree histogram (RED only, int4 grid-stride). No batch counting.
__global__ void k_hist(const int* __restrict__ dst, int E) {
    int stride = gridDim.x * blockDim.x;
    int t = blockIdx.x * blockDim.x + threadIdx.x;
    int E4 = E >> 2;
    const int4* d4 = (const int4*)dst;
    for (int e = t; e < E4; e += stride) {
        int4 v = d4[e];
        atomicAdd(&g_degi[v.x], 1); atomicAdd(&g_degi[v.y], 1);
        atomicAdd(&g_degi[v.z], 1); atomicAdd(&g_degi[v.w], 1);
    }
    for (int e = E4 * 4 + t; e < E; e += stride)
        atomicAdd(&g_degi[dst[e]], 1);
}

// Stream-2: w2l = W2 @ Wl ; b2wl = dot(b2, Wl). One block, 128 threads.
__global__ __launch_bounds__(128) void k_w2l(const float* __restrict__ W2,
                                             const float* __restrict__ Wl,
                                             const float* __restrict__ b2) {
    __shared__ float wls[FEAT];
    int t = threadIdx.x;
    wls[t] = Wl[t];
    __syncthreads();
    float acc = 0.0f;
    const float* row = W2 + (size_t)t * FEAT;
#pragma unroll 8
    for (int j = 0; j < FEAT; j++) acc += row[j] * wls[j];
    g_w2l[t] = acc;
    if (t == 0) {
        float c = 0.0f;
        for (int j = 0; j < FEAT; j++) c += b2[j] * wls[j];
        g_b2wl = c;
    }
}

// CSR slot allocation, warp-aggregated (one g_ctr atomic per warp) + dinv.
__global__ void k_alloc(int n) {
    int i = blockIdx.x * blockDim.x + threadIdx.x;
    int lane = threadIdx.x & 31;
    int deg = (i < n) ? g_degi[i] : 0;
    int incl = deg;
#pragma unroll
    for (int off = 1; off < 32; off <<= 1) {
        int v = __shfl_up_sync(0xFFFFFFFFu, incl, off);
        if (lane >= off) incl += v;
    }
    int total = __shfl_sync(0xFFFFFFFFu, incl, 31);
    int base = 0;
    if (lane == 31 && total > 0) base = atomicAdd(&g_ctr, total);
    base = __shfl_sync(0xFFFFFFFFu, base, 31);
    if (i < n) {
        int rs = base + incl - deg;
        g_rowstart[i] = rs;
        g_cursor[i] = rs;
        g_dinv[i] = rsqrtf(1.0f + (float)deg);
    }
}

// CSR fill (cursor atomics, int4 grid-stride with 4x batching).
__global__ void k_fill(const int* __restrict__ src, const int* __restrict__ dst, int E) {
    int stride = gridDim.x * blockDim.x;
    int t = blockIdx.x * blockDim.x + threadIdx.x;
    int E4 = E >> 2;
    const int4* d4 = (const int4*)dst;
    const int4* s4 = (const int4*)src;
    int e = t;
    for (; e + 3 * stride < E4; e += 4 * stride) {
        int4 da = d4[e];
        int4 db = d4[e + stride];
        int4 dc = d4[e + 2 * stride];
        int4 dd = d4[e + 3 * stride];
        int4 sa = s4[e];
        int4 sb = s4[e + stride];
        int4 sc = s4[e + 2 * stride];
        int4 sd = s4[e + 3 * stride];
        g_csrc[atomicAdd(&g_cursor[da.x], 1)] = sa.x;
        g_csrc[atomicAdd(&g_cursor[da.y], 1)] = sa.y;
        g_csrc[atomicAdd(&g_cursor[da.z], 1)] = sa.z;
        g_csrc[atomicAdd(&g_cursor[da.w], 1)] = sa.w;
        g_csrc[atomicAdd(&g_cursor[db.x], 1)] = sb.x;
        g_csrc[atomicAdd(&g_cursor[db.y], 1)] = sb.y;
        g_csrc[atomicAdd(&g_cursor[db.z], 1)] = sb.z;
        g_csrc[atomicAdd(&g_cursor[db.w], 1)] = sb.w;
        g_csrc[atomicAdd(&g_cursor[dc.x], 1)] = sc.x;
        g_csrc[atomicAdd(&g_cursor[dc.y], 1)] = sc.y;
        g_csrc[atomicAdd(&g_cursor[dc.z], 1)] = sc.z;
        g_csrc[atomicAdd(&g_cursor[dc.w], 1)] = sc.w;
        g_csrc[atomicAdd(&g_cursor[dd.x], 1)] = sd.x;
        g_csrc[atomicAdd(&g_cursor[dd.y], 1)] = sd.y;
        g_csrc[atomicAdd(&g_cursor[dd.z], 1)] = sd.z;
        g_csrc[atomicAdd(&g_cursor[dd.w], 1)] = sd.w;
    }
    for (; e < E4; e += stride) {
        int4 dv = d4[e];
        int4 sv = s4[e];
        g_csrc[atomicAdd(&g_cursor[dv.x], 1)] = sv.x;
        g_csrc[atomicAdd(&g_cursor[dv.y], 1)] = sv.y;
        g_csrc[atomicAdd(&g_cursor[dv.z], 1)] = sv.z;
        g_csrc[atomicAdd(&g_cursor[dv.w], 1)] = sv.w;
    }
    for (int q = E4 * 4 + t; q < E; q += stride)
        g_csrc[atomicAdd(&g_cursor[dst[q]], 1)] = src[q];
}

// ---------------------------------------------------------------------------
// HMMA GEMM: C[M,128] = fp16(A[M,128]) @ fp16(B[128,128]), fp32 accum,
// fp16 output. BM=64 rows/block, full K=128 resident in smem (48KB).
__global__ __launch_bounds__(256) void k_hgemm(const float* __restrict__ A,
                                               const float* __restrict__ B,
                                               __half* __restrict__ C, int M) {
    __shared__ __half Ah[64 * 128];
    __shared__ __half Bh[128 * 128];
    const int tid = threadIdx.x;
    const int block_row = blockIdx.x * 64;

    for (int i = tid; i < 4096; i += 256) {
        float4 v = ((const float4*)B)[i];
        ((__half2*)Bh)[i * 2 + 0] = __floats2half2_rn(v.x, v.y);
        ((__half2*)Bh)[i * 2 + 1] = __floats2half2_rn(v.z, v.w);
    }
    for (int i = tid; i < 2048; i += 256) {
        int row = i >> 5;
        float4 v = make_float4(0.f, 0.f, 0.f, 0.f);
        int gr = block_row + row;
        if (gr < M) v = ((const float4*)(A + (size_t)gr * 128))[i & 31];
        ((__half2*)Ah)[i * 2 + 0] = __floats2half2_rn(v.x, v.y);
        ((__half2*)Ah)[i * 2 + 1] = __floats2half2_rn(v.z, v.w);
    }
    __syncthreads();

    const int warp = tid >> 5;
    const int wm = warp >> 2;
    const int wn = warp & 3;

    wmma::fragment<wmma::accumulator, 16, 16, 16, float> acc[2][2];
#pragma unroll
    for (int i = 0; i < 2; i++)
#pragma unroll
        for (int j = 0; j < 2; j++) wmma::fill_fragment(acc[i][j], 0.0f);

#pragma unroll
    for (int k = 0; k < 128; k += 16) {
        wmma::fragment<wmma::matrix_a, 16, 16, 16, __half, wmma::row_major> a[2];
        wmma::fragment<wmma::matrix_b, 16, 16, 16, __half, wmma::row_major> b[2];
#pragma unroll
        for (int i = 0; i < 2; i++)
            wmma::load_matrix_sync(a[i], Ah + (wm * 32 + i * 16) * 128 + k, 128);
#pragma unroll
        for (int j = 0; j < 2; j++)
            wmma::load_matrix_sync(b[j], Bh + k * 128 + wn * 32 + j * 16, 128);
#pragma unroll
        for (int i = 0; i < 2; i++)
#pragma unroll
            for (int j = 0; j < 2; j++)
                wmma::mma_sync(acc[i][j], a[i], b[j], acc[i][j]);
    }
    __syncthreads();

    float* Cs = (float*)Bh;
#pragma unroll
    for (int i = 0; i < 2; i++)
#pragma unroll
        for (int j = 0; j < 2; j++)
            wmma::store_matrix_sync(Cs + (wm * 32 + i * 16) * 128 + wn * 32 + j * 16,
                                    acc[i][j], 128, wmma::mem_row_major);
    __syncthreads();

    for (int i = tid; i < 2048; i += 256) {
        int row = i >> 5;
        int gr = block_row + row;
        if (gr < M) {
            float4 v = ((const float4*)Cs)[i];
            __half2 h0 = __floats2half2_rn(v.x, v.y);
            __half2 h1 = __floats2half2_rn(v.z, v.w);
            uint2 o;
            o.x = *(unsigned*)&h0;
            o.y = *(unsigned*)&h1;
            ((uint2*)(C + (size_t)gr * 128))[i & 31] = o;
        }
    }
}

// ---------------------------------------------------------------------------
// CSR gather: 2 nodes per warp, 16 lanes x uint4 (8 halves) per node row.
//   acc = h[d]*dinv[d]^2 + sum_{s in N(d)} h[s]*dinv[s]*dinv[d]
//   g_w[d] = dinv[d] * dot(relu(acc + b1), w2l)
__global__ void k_gather1(const __half* __restrict__ h,
                          const float* __restrict__ bias, int n) {
    const int lane = threadIdx.x & 31;
    const int half = lane >> 4;
    const int hl = lane & 15;
    int warp = (blockIdx.x * blockDim.x + threadIdx.x) >> 5;
    int nwarps = (gridDim.x * blockDim.x) >> 5;

    float4 b0 = ((const float4*)bias)[hl * 2 + 0];
    float4 b1v = ((const float4*)bias)[hl * 2 + 1];
    float4 w0 = ((const float4*)g_w2l)[hl * 2 + 0];
    float4 w1 = ((const float4*)g_w2l)[hl * 2 + 1];

    for (int d = warp * 2 + half; d < n; d += nwarps * 2) {
        float dd = g_dinv[d];
        uint4 raw = ((const uint4*)(h + (size_t)d * FEAT))[hl];
        float2 p0 = __half22float2(*(const __half2*)&raw.x);
        float2 p1 = __half22float2(*(const __half2*)&raw.y);
        float2 p2 = __half22float2(*(const __half2*)&raw.z);
        float2 p3 = __half22float2(*(const __half2*)&raw.w);
        float sl = dd * dd;
        float a0 = p0.x * sl, a1 = p0.y * sl, a2 = p1.x * sl, a3 = p1.y * sl;
        float a4 = p2.x * sl, a5 = p2.y * sl, a6 = p3.x * sl, a7 = p3.y * sl;

        int r0 = g_rowstart[d];
        int r1 = r0 + g_degi[d];
        for (int r = r0; r < r1; r++) {
            int s = g_csrc[r];
            float nrm = g_dinv[s] * dd;
            uint4 rv = ((const uint4*)(h + (size_t)s * FEAT))[hl];
            float2 q0 = __half22float2(*(const __half2*)&rv.x);
            float2 q1 = __half22float2(*(const __half2*)&rv.y);
            float2 q2 = __half22float2(*(const __half2*)&rv.z);
            float2 q3 = __half22float2(*(const __half2*)&rv.w);
            a0 += q0.x * nrm; a1 += q0.y * nrm;
            a2 += q1.x * nrm; a3 += q1.y * nrm;
            a4 += q2.x * nrm; a5 += q2.y * nrm;
            a6 += q3.x * nrm; a7 += q3.y * nrm;
        }
        float sdot;
        sdot  = fmaxf(a0 + b0.x, 0.f) * w0.x;
        sdot += fmaxf(a1 + b0.y, 0.f) * w0.y;
        sdot += fmaxf(a2 + b0.z, 0.f) * w0.z;
        sdot += fmaxf(a3 + b0.w, 0.f) * w0.w;
        sdot += fmaxf(a4 + b1v.x, 0.f) * w1.x;
        sdot += fmaxf(a5 + b1v.y, 0.f) * w1.y;
        sdot += fmaxf(a6 + b1v.z, 0.f) * w1.z;
        sdot += fmaxf(a7 + b1v.w, 0.f) * w1.w;
#pragma unroll
        for (int off = 8; off > 0; off >>= 1)
            sdot += __shfl_xor_sync(0xFFFFFFFFu, sdot, off);
        if (hl == 0) g_w[d] = dd * sdot;
    }
}

// Scalar aggregation + pool: gsum[batch[d]] += dinv[d]*(w[d] + sum_s w[s]).
__global__ void k_scalar(const int* __restrict__ batch, int n) {
    int stride = gridDim.x * blockDim.x;
    for (int d = blockIdx.x * blockDim.x + threadIdx.x; d < n; d += stride) {
        float s = g_w[d];
        int r0 = g_rowstart[d];
        int r1 = r0 + g_degi[d];
        for (int r = r0; r < r1; r++) s += g_w[g_csrc[r]];
        atomicAdd(&g_gsum[batch[d]], g_dinv[d] * s);
    }
}

// out[g] = gsum[g]/max(cnt,1) + dot(b2, Wl) + bl.
// batch is SORTED, so cnt[g] = lower_bound(g+1) - lower_bound(g).
__global__ void k_out(const int* __restrict__ batch, const float* __restrict__ bl,
                      float* __restrict__ out, int n) {
    int g = blockIdx.x * blockDim.x + threadIdx.x;
    if (g < GMAX) {
        int lo = 0, hi = n;
        while (lo < hi) { int m = (lo + hi) >> 1; if (batch[m] < g) lo = m + 1; else hi = m; }
        int lo2 = lo, hi2 = n;
        while (lo2 < hi2) { int m = (lo2 + hi2) >> 1; if (batch[m] < g + 1) lo2 = m + 1; else hi2 = m; }
        float cnt = (float)(lo2 - lo);
        out[g] = g_gsum[g] / fmaxf(cnt, 1.0f) + g_b2wl + bl[0];
    }
}

// ---------------------------------------------------------------------------
static cudaStream_t g_s2 = nullptr;
static cudaEvent_t g_evFork = nullptr, g_evJoin = nullptr;

extern "C" void kernel_launch(void* const* d_in, const int* in_sizes, int n_in,
                              void* d_out, int out_size) {
    const float* x     = (const float*)d_in[0];
    const int*   ei    = (const int*)d_in[1];
    const int*   batch = (const int*)d_in[3];
    const float* W1    = (const float*)d_in[4];
    const float* b1    = (const float*)d_in[5];
    const float* W2    = (const float*)d_in[6];
    const float* b2    = (const float*)d_in[7];
    const float* Wl    = (const float*)d_in[8];
    const float* bl    = (const float*)d_in[9];
    float* out = (float*)d_out;

    int n = in_sizes[0] / FEAT;
    int E = in_sizes[1] / 2;
    if (n > NMAX) n = NMAX;
    if (E > EMAX) E = EMAX;
    const int* src = ei;
    const int* dst = ei + E;

    __half* bufH;
    cudaGetSymbolAddress((void**)&bufH, g_bufH);

    if (!g_s2) {
        cudaStreamCreateWithFlags(&g_s2, cudaStreamNonBlocking);
        cudaEventCreateWithFlags(&g_evFork, cudaEventDisableTiming);
        cudaEventCreateWithFlags(&g_evJoin, cudaEventDisableTiming);
    }

    const int T = 256;
    int nBlocksN   = (n + T - 1) / T;
    int gemmBlocks = (n + 63) / 64;
    int E4 = E >> 2;
    int fillBlocks = (E4 + 2 * T - 1) / (2 * T);

    // Fork: stream 2 = w2l + GEMM ONLY (identical to the 205.9us champion).
    cudaEventRecord(g_evFork, 0);
    cudaStreamWaitEvent(g_s2, g_evFork, 0);
    k_w2l<<<1, 128, 0, g_s2>>>(W2, Wl, b2);
    k_hgemm<<<gemmBlocks, T, 0, g_s2>>>(x, W1, bufH, n);
    cudaEventRecord(g_evJoin, g_s2);

    // Main stream: compact CSR build (hist is pure RED now).
    k_init<<<nBlocksN, T>>>(n);
    k_hist<<<1024, T>>>(dst, E);
    k_alloc<<<nBlocksN, T>>>(n);
    k_fill<<<fillBlocks, T>>>(src, dst, E);

    // Join, then gather + scalar + head.
    cudaStreamWaitEvent(0, g_evJoin, 0);
    k_gather1<<<2048, T>>>(bufH, b1, n);
    k_scalar<<<1024, T>>>(batch, n);
    k_out<<<(GMAX + T - 1) / T, T>>>(batch, bl, out, n);
}